// round 1
// baseline (speedup 1.0000x reference)
#include <cuda_runtime.h>
#include <math.h>

#define T_   64
#define B_   256
#define NIN_ 1024
#define H_   2048
#define G_   8192   // 4*H

__device__ float g_A[(size_t)T_ * B_ * G_];
__device__ float g_HW[(size_t)B_ * G_];
__device__ float g_c[(size_t)B_ * H_];
__device__ float g_h[(size_t)B_ * H_];

#define BM 64
#define BN 64
#define BK 16

__global__ __launch_bounds__(256) void sgemm_kernel(
    const float* __restrict__ A, const float* __restrict__ B,
    float* __restrict__ C, int M, int N, int K)
{
    __shared__ float As[BK][BM + 4];
    __shared__ float Bs[BK][BN];

    const int tid  = threadIdx.x;
    const int tcol = tid & 15;
    const int trow = tid >> 4;
    const int aRow = tid >> 2;
    const int aCol = (tid & 3) << 2;
    const int bRow = tid >> 4;
    const int bCol = (tid & 15) << 2;

    const float* Ab = A + (size_t)(blockIdx.y * BM) * K;
    const float* Bb = B + (size_t)blockIdx.x * BN;

    float acc[4][4] = {};

    for (int k0 = 0; k0 < K; k0 += BK) {
        float4 av = *(const float4*)(Ab + (size_t)aRow * K + k0 + aCol);
        As[aCol + 0][aRow] = av.x;
        As[aCol + 1][aRow] = av.y;
        As[aCol + 2][aRow] = av.z;
        As[aCol + 3][aRow] = av.w;
        float4 bv = *(const float4*)(Bb + (size_t)(k0 + bRow) * N + bCol);
        *(float4*)&Bs[bRow][bCol] = bv;
        __syncthreads();

        #pragma unroll
        for (int k = 0; k < BK; k++) {
            float4 a4 = *(const float4*)&As[k][trow * 4];
            float4 b4 = *(const float4*)&Bs[k][tcol * 4];
            float ar[4] = {a4.x, a4.y, a4.z, a4.w};
            float br[4] = {b4.x, b4.y, b4.z, b4.w};
            #pragma unroll
            for (int i = 0; i < 4; i++)
                #pragma unroll
                for (int j = 0; j < 4; j++)
                    acc[i][j] += ar[i] * br[j];
        }
        __syncthreads();
    }

    float* Cb = C + (size_t)(blockIdx.y * BM + trow * 4) * N
                  + (size_t)blockIdx.x * BN + tcol * 4;
    #pragma unroll
    for (int i = 0; i < 4; i++) {
        float4 v = make_float4(acc[i][0], acc[i][1], acc[i][2], acc[i][3]);
        *(float4*)(Cb + (size_t)i * N) = v;
    }
}

__device__ __forceinline__ void blk_reduce2(float& s, float& s2)
{
    __shared__ float rbuf[2][8];
    const int lane = threadIdx.x & 31;
    const int warp = threadIdx.x >> 5;
    #pragma unroll
    for (int o = 16; o; o >>= 1) {
        s  += __shfl_down_sync(0xffffffffu, s,  o);
        s2 += __shfl_down_sync(0xffffffffu, s2, o);
    }
    if (lane == 0) { rbuf[0][warp] = s; rbuf[1][warp] = s2; }
    __syncthreads();
    if (warp == 0) {
        s  = (lane < 8) ? rbuf[0][lane] : 0.f;
        s2 = (lane < 8) ? rbuf[1][lane] : 0.f;
        #pragma unroll
        for (int o = 4; o; o >>= 1) {
            s  += __shfl_down_sync(0xffffffffu, s,  o);
            s2 += __shfl_down_sync(0xffffffffu, s2, o);
        }
        if (lane == 0) { rbuf[0][0] = s; rbuf[1][0] = s2; }
    }
    __syncthreads();
    s  = rbuf[0][0];
    s2 = rbuf[1][0];
    __syncthreads();
}

__global__ __launch_bounds__(256) void ln_rows_add_kernel(
    const float* __restrict__ Cin, const float* __restrict__ gamma,
    const float* __restrict__ beta, const float* __restrict__ bias,
    float* __restrict__ Aout)
{
    const int row = blockIdx.x;
    const float* x = Cin + (size_t)row * G_;
    float s = 0.f, s2 = 0.f;
    for (int j = threadIdx.x; j < G_; j += 256) {
        float v = x[j]; s += v; s2 += v * v;
    }
    blk_reduce2(s, s2);
    const float inv = 1.f / (float)G_;
    float mu   = s * inv;
    float var  = s2 * inv - mu * mu;
    float rstd = rsqrtf(var + 1e-5f);
    float* o = Aout + (size_t)row * G_;
    for (int j = threadIdx.x; j < G_; j += 256) {
        o[j] = (x[j] - mu) * rstd * gamma[j] + beta[j] + bias[j];
    }
}

__global__ void init_state_kernel(const float* __restrict__ init)
{
    int idx = blockIdx.x * blockDim.x + threadIdx.x;
    int b = idx >> 11;
    int j = idx & (H_ - 1);
    size_t base = (size_t)b * T_ * 2 * H_;
    g_c[idx] = init[base + j];
    g_h[idx] = init[base + H_ + j];
}

__global__ void mask_h_kernel(int t, const float* __restrict__ mask)
{
    int idx = blockIdx.x * blockDim.x + threadIdx.x;
    int b = idx >> 11;
    g_h[idx] *= (1.f - mask[t * B_ + b]);
}

__global__ __launch_bounds__(256) void cell_kernel(
    int t, const float* __restrict__ mask,
    const float* __restrict__ A,
    const float* __restrict__ gh, const float* __restrict__ bh,
    const float* __restrict__ gc, const float* __restrict__ bc,
    float* __restrict__ hs)
{
    __shared__ float so[H_];
    const int b = blockIdx.x;
    const float keep = 1.f - mask[t * B_ + b];
    const float* hw = g_HW + (size_t)b * G_;
    const float* a  = A + ((size_t)t * B_ + b) * G_;

    float s = 0.f, s2 = 0.f;
    for (int j = threadIdx.x; j < G_; j += 256) {
        float v = hw[j]; s += v; s2 += v * v;
    }
    blk_reduce2(s, s2);
    const float invG = 1.f / (float)G_;
    float mu   = s * invG;
    float rstd = rsqrtf(s2 * invG - mu * mu + 1e-5f);

    float cs = 0.f, cs2 = 0.f;
    for (int j = threadIdx.x; j < H_; j += 256) {
        float zi = a[j]          + (hw[j]          - mu) * rstd * gh[j]          + bh[j];
        float zf = a[H_ + j]     + (hw[H_ + j]     - mu) * rstd * gh[H_ + j]     + bh[H_ + j];
        float zo = a[2 * H_ + j] + (hw[2 * H_ + j] - mu) * rstd * gh[2 * H_ + j] + bh[2 * H_ + j];
        float zu = a[3 * H_ + j] + (hw[3 * H_ + j] - mu) * rstd * gh[3 * H_ + j] + bh[3 * H_ + j];
        float ig = 1.f / (1.f + expf(-zi));
        float fg = 1.f / (1.f + expf(-zf));
        float og = 1.f / (1.f + expf(-zo));
        float ug = tanhf(zu);
        float cn = fg * (g_c[(size_t)b * H_ + j] * keep) + ig * ug;
        g_c[(size_t)b * H_ + j] = cn;
        so[j] = og;
        cs += cn; cs2 += cn * cn;
    }
    blk_reduce2(cs, cs2);
    const float invH = 1.f / (float)H_;
    float muc   = cs * invH;
    float rstdc = rsqrtf(cs2 * invH - muc * muc + 1e-5f);

    for (int j = threadIdx.x; j < H_; j += 256) {
        float cn = g_c[(size_t)b * H_ + j];
        float hn = so[j] * tanhf((cn - muc) * rstdc * gc[j] + bc[j]);
        hs[((size_t)t * B_ + b) * H_ + j] = hn;
        g_h[(size_t)b * H_ + j] = hn;
    }
}

__global__ void write_state_kernel(float* __restrict__ sout)
{
    int idx = blockIdx.x * blockDim.x + threadIdx.x;
    int b = idx >> 11;
    int j = idx & (H_ - 1);
    sout[(size_t)b * 2 * H_ + j]      = g_c[idx];
    sout[(size_t)b * 2 * H_ + H_ + j] = g_h[idx];
}

extern "C" void kernel_launch(void* const* d_in, const int* in_sizes, int n_in,
                              void* d_out, int out_size)
{
    const float* x    = (const float*)d_in[0];
    const float* mask = (const float*)d_in[1];
    const float* init = (const float*)d_in[2];
    const float* wx   = (const float*)d_in[3];
    const float* wh   = (const float*)d_in[4];
    const float* bvec = (const float*)d_in[5];
    const float* gx   = (const float*)d_in[6];
    const float* bx   = (const float*)d_in[7];
    const float* gh   = (const float*)d_in[8];
    const float* bh   = (const float*)d_in[9];
    const float* gc   = (const float*)d_in[10];
    const float* bc   = (const float*)d_in[11];

    float* out  = (float*)d_out;
    float* hs   = out;
    float* sout = out + (size_t)T_ * B_ * H_;

    float *Abuf, *HWbuf, *cbuf, *hbuf;
    cudaGetSymbolAddress((void**)&Abuf,  g_A);
    cudaGetSymbolAddress((void**)&HWbuf, g_HW);
    cudaGetSymbolAddress((void**)&cbuf,  g_c);
    cudaGetSymbolAddress((void**)&hbuf,  g_h);

    sgemm_kernel<<<dim3(G_ / BN, (T_ * B_) / BM), 256>>>(x, wx, Abuf, T_ * B_, G_, NIN_);
    ln_rows_add_kernel<<<T_ * B_, 256>>>(Abuf, gx, bx, bvec, Abuf);

    init_state_kernel<<<(B_ * H_) / 256, 256>>>(init);

    for (int t = 0; t < T_; t++) {
        mask_h_kernel<<<(B_ * H_) / 256, 256>>>(t, mask);
        sgemm_kernel<<<dim3(G_ / BN, B_ / BM), 256>>>(hbuf, wh, HWbuf, B_, G_, H_);
        cell_kernel<<<B_, 256>>>(t, mask, Abuf, gh, bh, gc, bc, hs);
    }

    write_state_kernel<<<(B_ * H_) / 256, 256>>>(sout);
}